// round 1
// baseline (speedup 1.0000x reference)
#include <cuda_runtime.h>
#include <math.h>

// Problem constants
#define B_SZ   512
#define T_SZ   128
#define HID    1024
#define EMB    512
#define GATES  4096   // 4*HID
#define KCELL  1536   // EMB + HID

// Persistent scratch (static __device__ arrays: allocation-free rule)
__device__ float g_h[B_SZ * HID];
__device__ float g_c[B_SZ * HID];
__device__ float g_gates[B_SZ * GATES];

// Tiling
#define BM 128
#define BN 128
#define BK 16
// 256 threads, each computes an 8x8 micro-tile.

// MODE: 0 = plain A from param, 1 = LSTM gather ([emb(message[:,t]) | g_h]), 2 = A = g_h
template<int MODE>
__global__ __launch_bounds__(256)
void gemm_k(const float* __restrict__ A,
            const float* __restrict__ embed,
            const int*   __restrict__ message,
            int t,
            const float* __restrict__ W,     // [K, N] row-major
            const float* __restrict__ bias,  // [N]
            float* __restrict__ Cout,        // [M, N] (ignored for MODE 1)
            int N, int K)
{
    __shared__ float As[BK][BM + 4];  // transposed A tile, padded
    __shared__ float Bs[BK][BN];

    const int tid = threadIdx.x;
    const int bm = blockIdx.y * BM;
    const int bn = blockIdx.x * BN;

    // --- A-tile load assignment: 2 float4 per thread ---
    const int ar0 = tid >> 2;          // rows 0..63
    const int ar1 = ar0 + 64;          // rows 64..127
    const int akq = (tid & 3) * 4;     // k-offset within tile: 0,4,8,12

    const float* aE0;
    const float* aE1;
    const float* aH0 = nullptr;
    const float* aH1 = nullptr;

    if (MODE == 1) {
        const int e0 = message[(bm + ar0) * T_SZ + t];
        const int e1 = message[(bm + ar1) * T_SZ + t];
        aE0 = embed + (size_t)e0 * EMB;
        aE1 = embed + (size_t)e1 * EMB;
        aH0 = g_h + (size_t)(bm + ar0) * HID;
        aH1 = g_h + (size_t)(bm + ar1) * HID;
    } else {
        const float* Ab = (MODE == 2) ? (const float*)g_h : A;
        aE0 = Ab + (size_t)(bm + ar0) * K;
        aE1 = Ab + (size_t)(bm + ar1) * K;
    }

    // --- B-tile load assignment: 2 float4 per thread ---
    const int br0 = tid >> 5;          // rows 0..7
    const int br1 = br0 + 8;           // rows 8..15
    const int bc  = (tid & 31) * 4;    // col quad

    // --- compute assignment ---
    const int tm = (tid >> 4) * 8;     // 0..120
    const int tn = (tid & 15) * 8;     // 0..120

    float acc[8][8];
    #pragma unroll
    for (int i = 0; i < 8; i++)
        #pragma unroll
        for (int j = 0; j < 8; j++) acc[i][j] = 0.0f;

    for (int k0 = 0; k0 < K; k0 += BK) {
        const float* p0;
        const float* p1;
        if (MODE == 1) {
            if (k0 < EMB) { p0 = aE0 + k0;         p1 = aE1 + k0; }
            else          { p0 = aH0 + (k0 - EMB); p1 = aH1 + (k0 - EMB); }
        } else {
            p0 = aE0 + k0;
            p1 = aE1 + k0;
        }

        const float4 va0 = *(const float4*)(p0 + akq);
        const float4 va1 = *(const float4*)(p1 + akq);
        const float4 vb0 = *(const float4*)(W + (size_t)(k0 + br0) * N + bn + bc);
        const float4 vb1 = *(const float4*)(W + (size_t)(k0 + br1) * N + bn + bc);

        As[akq + 0][ar0] = va0.x; As[akq + 1][ar0] = va0.y;
        As[akq + 2][ar0] = va0.z; As[akq + 3][ar0] = va0.w;
        As[akq + 0][ar1] = va1.x; As[akq + 1][ar1] = va1.y;
        As[akq + 2][ar1] = va1.z; As[akq + 3][ar1] = va1.w;
        *(float4*)&Bs[br0][bc] = vb0;
        *(float4*)&Bs[br1][bc] = vb1;

        __syncthreads();

        #pragma unroll
        for (int kk = 0; kk < BK; kk++) {
            float a[8], b[8];
            *(float4*)&a[0] = *(const float4*)&As[kk][tm];
            *(float4*)&a[4] = *(const float4*)&As[kk][tm + 4];
            *(float4*)&b[0] = *(const float4*)&Bs[kk][tn];
            *(float4*)&b[4] = *(const float4*)&Bs[kk][tn + 4];
            #pragma unroll
            for (int i = 0; i < 8; i++)
                #pragma unroll
                for (int j = 0; j < 8; j++)
                    acc[i][j] = fmaf(a[i], b[j], acc[i][j]);
        }
        __syncthreads();
    }

    // epilogue: add bias, store
    float bia[8];
    *(float4*)&bia[0] = *(const float4*)(bias + bn + tn);
    *(float4*)&bia[4] = *(const float4*)(bias + bn + tn + 4);

    float* C = (MODE == 1) ? g_gates : Cout;
    #pragma unroll
    for (int i = 0; i < 8; i++) {
        float4 o0, o1;
        o0.x = acc[i][0] + bia[0]; o0.y = acc[i][1] + bia[1];
        o0.z = acc[i][2] + bia[2]; o0.w = acc[i][3] + bia[3];
        o1.x = acc[i][4] + bia[4]; o1.y = acc[i][5] + bia[5];
        o1.z = acc[i][6] + bia[6]; o1.w = acc[i][7] + bia[7];
        float* crow = C + (size_t)(bm + tm + i) * N + bn + tn;
        *(float4*)(crow)     = o0;
        *(float4*)(crow + 4) = o1;
    }
}

__device__ __forceinline__ float sigm(float x) {
    return 1.0f / (1.0f + expf(-x));
}

__global__ void lstm_pointwise()
{
    const int idx = blockIdx.x * blockDim.x + threadIdx.x;   // 0 .. B*HID
    if (idx >= B_SZ * HID) return;
    const int b  = idx >> 10;        // /1024
    const int hh = idx & 1023;
    const float* g = g_gates + (size_t)b * GATES;
    const float vi = g[hh];
    const float vg = g[HID + hh];
    const float vf = g[2 * HID + hh];
    const float vo = g[3 * HID + hh];

    const float f = sigm(vf + 1.0f);
    const float c = f * g_c[idx] + sigm(vi) * tanhf(vg);
    g_c[idx] = c;
    g_h[idx] = sigm(vo) * tanhf(c);
}

__global__ void zero_hc()
{
    const int idx = blockIdx.x * blockDim.x + threadIdx.x;
    if (idx < B_SZ * HID) {
        g_h[idx] = 0.0f;
        g_c[idx] = 0.0f;
    }
}

extern "C" void kernel_launch(void* const* d_in, const int* in_sizes, int n_in,
                              void* d_out, int out_size)
{
    const float* images  = (const float*)d_in[0];   // [512, 2048]
    const float* embed   = (const float*)d_in[1];   // [1024, 512]
    const float* W_cell  = (const float*)d_in[2];   // [1536, 4096]
    const float* b_cell  = (const float*)d_in[3];   // [4096]
    const float* W_img   = (const float*)d_in[4];   // [2048, 1024]
    const float* b_img   = (const float*)d_in[5];   // [1024]
    const float* W_hid   = (const float*)d_in[6];   // [1024, 1024]
    const float* b_hid   = (const float*)d_in[7];   // [1024]
    const int*   message = (const int*)d_in[8];     // [512, 128]
    float* out = (float*)d_out;                     // [2 * 512 * 1024]

    (void)in_sizes; (void)n_in; (void)out_size;

    // reset recurrent state (deterministic across graph replays)
    zero_hc<<<(B_SZ * HID + 255) / 256, 256>>>();

    // images_encoded = images @ W_img + b_img  (independent of the loop)
    gemm_k<0><<<dim3(1024 / BN, B_SZ / BM), 256>>>(
        images, nullptr, nullptr, 0, W_img, b_img, out, 1024, 2048);

    // 128 sequential LSTM steps
    const dim3 grid_lstm(GATES / BN, B_SZ / BM);   // 32 x 4
    for (int t = 0; t < T_SZ; t++) {
        gemm_k<1><<<grid_lstm, 256>>>(
            nullptr, embed, message, t, W_cell, b_cell, nullptr, GATES, KCELL);
        lstm_pointwise<<<(B_SZ * HID + 255) / 256, 256>>>();
    }

    // hidden_encoded = h @ W_hid + b_hid
    gemm_k<2><<<dim3(1024 / BN, B_SZ / BM), 256>>>(
        nullptr, nullptr, nullptr, 0, W_hid, b_hid, out + (size_t)B_SZ * HID,
        1024, 1024);
}

// round 3
// speedup vs baseline: 2.0137x; 2.0137x over previous
#include <cuda_runtime.h>
#include <cuda_bf16.h>
#include <math.h>
#include <stdint.h>

#define B_SZ   512
#define T_SZ   128
#define HID    1024
#define EMB    512
#define GATES  4096
#define KCELL  1536

// ---------------- device scratch (allocation-free) ----------------
__device__ __nv_bfloat16 g_Whi[GATES * KCELL];          // [p][k] permuted N-major
__device__ __nv_bfloat16 g_Wlo[GATES * KCELL];
__device__ __nv_bfloat16 g_Xhi[(size_t)T_SZ * B_SZ * EMB];  // [t][b][k] 64MB
__device__ __nv_bfloat16 g_Xlo[(size_t)T_SZ * B_SZ * EMB];
__device__ __nv_bfloat16 g_hbhi[2][B_SZ * HID];         // double-buffered h (bf16 hi/lo)
__device__ __nv_bfloat16 g_hblo[2][B_SZ * HID];
__device__ float g_hf[B_SZ * HID];                      // fp32 h (for final projection)
__device__ float g_c[B_SZ * HID];
__device__ float g_bp[GATES];                           // permuted bias (+1 folded into f)

// ---------------- helpers ----------------
__device__ __forceinline__ uint32_t smem_u32(const void* p) {
    uint32_t r;
    asm("{ .reg .u64 t; cvta.to.shared.u64 t, %1; cvt.u32.u64 %0, t; }" : "=r"(r) : "l"(p));
    return r;
}
__device__ __forceinline__ void cpa16(uint32_t dst, const void* src) {
    asm volatile("cp.async.cg.shared.global [%0], [%1], 16;" :: "r"(dst), "l"(src) : "memory");
}
#define CP_COMMIT() asm volatile("cp.async.commit_group;" ::: "memory")
#define CP_WAIT1()  asm volatile("cp.async.wait_group 1;" ::: "memory")
#define CP_WAIT0()  asm volatile("cp.async.wait_group 0;" ::: "memory")

#define LDMX4(r, addr) \
    asm volatile("ldmatrix.sync.aligned.m8n8.x4.shared.b16 {%0,%1,%2,%3}, [%4];" \
        : "=r"((r)[0]), "=r"((r)[1]), "=r"((r)[2]), "=r"((r)[3]) : "r"(addr))

#define MMA(acc, a, b0, b1) \
    asm volatile("mma.sync.aligned.m16n8k16.row.col.f32.bf16.bf16.f32 " \
        "{%0,%1,%2,%3}, {%4,%5,%6,%7}, {%8,%9}, {%0,%1,%2,%3};" \
        : "+f"((acc)[0]), "+f"((acc)[1]), "+f"((acc)[2]), "+f"((acc)[3]) \
        : "r"((a)[0]), "r"((a)[1]), "r"((a)[2]), "r"((a)[3]), "r"(b0), "r"(b1))

#define SW(o) ((uint32_t)(o) ^ ((((uint32_t)(o)) >> 3) & 0x70))

__device__ __forceinline__ float sigm(float x) { return 1.0f / (1.0f + __expf(-x)); }
__device__ __forceinline__ float tanh_f(float x) {
    float e = __expf(2.0f * x);
    return 1.0f - 2.0f / (e + 1.0f);
}

// smem stage layout: 4 regions of 16KB (128 rows x 128B), 2 stages
#define OFF_AHI   0
#define OFF_ALO   16384
#define OFF_BHI   32768
#define OFF_BLO   49152
#define STAGE_SZ  65536
#define STEP_SMEM (2 * STAGE_SZ)   // 131072

// ================= fused LSTM step: bf16 3-pass mma.sync GEMM + pointwise =================
__global__ void __launch_bounds__(256, 1)
lstm_step(int t)
{
    extern __shared__ __align__(1024) char smem[];
    const uint32_t sm = smem_u32(smem);
    const int tid  = threadIdx.x;
    const int lane = tid & 31;
    const int wid  = tid >> 5;
    const int bx   = blockIdx.x;           // n-tile 0..31 (permuted cols)
    const int bm   = blockIdx.y * 128;     // m-tile base row

    // ---- per-thread global source pointers ----
    const int r    = tid >> 1;             // 0..127 tile row
    const int half = tid & 1;              // which 64B half of the 128B row
    const __nv_bfloat16* aXhi = g_Xhi + ((size_t)t * B_SZ + bm + r) * EMB;
    const __nv_bfloat16* aXlo = g_Xlo + ((size_t)t * B_SZ + bm + r) * EMB;
    const __nv_bfloat16* aHhi = g_hbhi[t & 1] + (size_t)(bm + r) * HID;
    const __nv_bfloat16* aHlo = g_hblo[t & 1] + (size_t)(bm + r) * HID;
    const char* bWhi = (const char*)(g_Whi + (size_t)(bx * 128 + r) * KCELL);
    const char* bWlo = (const char*)(g_Wlo + (size_t)(bx * 128 + r) * KCELL);

    // ---- warp compute layout: 2(M) x 4(N) warps; warp tile 64x32 ----
    const int wm = (wid >> 2) * 64;
    const int wn = (wid & 3) * 32;

    float acc[4][4][4];
    #pragma unroll
    for (int i = 0; i < 4; i++)
        #pragma unroll
        for (int j = 0; j < 4; j++)
            #pragma unroll
            for (int k = 0; k < 4; k++) acc[i][j][k] = 0.0f;

    // ldmatrix per-lane row/col components (within-stage byte offsets built per use)
    const int aRow = (lane & 15);                              // + wm + mi*16
    const int aSel = ((lane >> 4) & 1) * 16;                   // k8 select (bytes)
    const int bRowBase = (lane & 7) + ((lane >> 4) & 1) * 8;   // + wn + nj*16
    const int bSel = ((lane >> 3) & 1) * 16;

    // ---- prefetch chunk 0 ----
    {
        const uint32_t dst = sm;  // stage 0
        #pragma unroll
        for (int u = 0; u < 4; u++) {
            const uint32_t off = SW(r * 128 + half * 64 + u * 16);
            const int gb = half * 64 + u * 16;
            cpa16(dst + OFF_AHI + off, (const char*)aXhi + gb);
            cpa16(dst + OFF_ALO + off, (const char*)aXlo + gb);
            cpa16(dst + OFF_BHI + off, bWhi + gb);
            cpa16(dst + OFF_BLO + off, bWlo + gb);
        }
        CP_COMMIT();
    }

    #pragma unroll 1
    for (int c = 0; c < 24; c++) {
        __syncthreads();   // all warps done computing chunk c-1 (buffer reuse safe)

        if (c + 1 < 24) {
            const int k0 = (c + 1) * 64;
            const char* sAhi;
            const char* sAlo;
            if (k0 < EMB) { sAhi = (const char*)(aXhi + k0); sAlo = (const char*)(aXlo + k0); }
            else          { sAhi = (const char*)(aHhi + (k0 - EMB)); sAlo = (const char*)(aHlo + (k0 - EMB)); }
            const uint32_t dst = sm + ((c + 1) & 1) * STAGE_SZ;
            const int kb = k0 * 2;
            #pragma unroll
            for (int u = 0; u < 4; u++) {
                const uint32_t off = SW(r * 128 + half * 64 + u * 16);
                const int gb = half * 64 + u * 16;
                cpa16(dst + OFF_AHI + off, sAhi + gb);
                cpa16(dst + OFF_ALO + off, sAlo + gb);
                cpa16(dst + OFF_BHI + off, bWhi + kb + gb);
                cpa16(dst + OFF_BLO + off, bWlo + kb + gb);
            }
            CP_COMMIT();
            CP_WAIT1();
        } else {
            CP_WAIT0();
        }
        __syncthreads();   // chunk c data visible to all warps

        const uint32_t stage = sm + (c & 1) * STAGE_SZ;
        #pragma unroll
        for (int k16 = 0; k16 < 4; k16++) {
            const int kb = k16 * 32;
            uint32_t ah[4][4], al[4][4], bh[2][4], bl[2][4];
            #pragma unroll
            for (int mi = 0; mi < 4; mi++) {
                const uint32_t ao = SW((wm + mi * 16 + aRow) * 128 + kb + aSel);
                LDMX4(ah[mi], stage + OFF_AHI + ao);
                LDMX4(al[mi], stage + OFF_ALO + ao);
            }
            #pragma unroll
            for (int nj = 0; nj < 2; nj++) {
                const uint32_t bo = SW((wn + nj * 16 + bRowBase) * 128 + kb + bSel);
                LDMX4(bh[nj], stage + OFF_BHI + bo);
                LDMX4(bl[nj], stage + OFF_BLO + bo);
            }
            #pragma unroll
            for (int mi = 0; mi < 4; mi++) {
                #pragma unroll
                for (int n8 = 0; n8 < 4; n8++) {
                    const uint32_t bh0 = bh[n8 >> 1][(n8 & 1) * 2];
                    const uint32_t bh1 = bh[n8 >> 1][(n8 & 1) * 2 + 1];
                    const uint32_t bl0 = bl[n8 >> 1][(n8 & 1) * 2];
                    const uint32_t bl1 = bl[n8 >> 1][(n8 & 1) * 2 + 1];
                    MMA(acc[mi][n8], ah[mi], bh0, bh1);
                    MMA(acc[mi][n8], al[mi], bh0, bh1);
                    MMA(acc[mi][n8], ah[mi], bl0, bl1);
                }
            }
        }
    }

    // ---- stage accumulators to smem (fp32, stride 132) ----
    __syncthreads();
    float* smC = (float*)smem;
    #pragma unroll
    for (int mi = 0; mi < 4; mi++) {
        #pragma unroll
        for (int n8 = 0; n8 < 4; n8++) {
            const int row = wm + mi * 16 + (lane >> 2);
            const int col = wn + n8 * 8 + (lane & 3) * 2;
            smC[row * 132 + col]         = acc[mi][n8][0];
            smC[row * 132 + col + 1]     = acc[mi][n8][1];
            smC[(row + 8) * 132 + col]     = acc[mi][n8][2];
            smC[(row + 8) * 132 + col + 1] = acc[mi][n8][3];
        }
    }
    __syncthreads();

    // ---- fused LSTM pointwise epilogue ----
    if (tid < 128) {
        const int row = bm + tid;
        const float* cr = smC + tid * 132;
        const float* bp = g_bp + bx * 128;
        float* crow = g_c + (size_t)row * HID + bx * 32;
        float* hrow = g_hf + (size_t)row * HID + bx * 32;
        __nv_bfloat16* hh = g_hbhi[(t + 1) & 1] + (size_t)row * HID + bx * 32;
        __nv_bfloat16* hl = g_hblo[(t + 1) & 1] + (size_t)row * HID + bx * 32;
        #pragma unroll 8
        for (int l = 0; l < 32; l++) {
            const float iv = cr[l]      + bp[l];
            const float gv = cr[32 + l] + bp[32 + l];
            const float fv = cr[64 + l] + bp[64 + l];   // +1 folded into bias
            const float ov = cr[96 + l] + bp[96 + l];
            const float cc = sigm(fv) * crow[l] + sigm(iv) * tanh_f(gv);
            const float hv = sigm(ov) * tanh_f(cc);
            crow[l] = cc;
            hrow[l] = hv;
            const __nv_bfloat16 hi = __float2bfloat16(hv);
            hh[l] = hi;
            hl[l] = __float2bfloat16(hv - __bfloat162float(hi));
        }
    }
}

// ================= prep kernels =================
__global__ void prep_w(const float* __restrict__ W)
{
    int idx = blockIdx.x * blockDim.x + threadIdx.x;
    if (idx >= KCELL * GATES) return;
    const int ncol = idx / KCELL;
    const int k    = idx % KCELL;
    const int q = (ncol >> 5) & 3, j = ncol >> 7, l = ncol & 31;
    const int n = q * 1024 + j * 32 + l;
    const float w = W[(size_t)k * GATES + n];
    const __nv_bfloat16 hi = __float2bfloat16(w);
    g_Whi[idx] = hi;
    g_Wlo[idx] = __float2bfloat16(w - __bfloat162float(hi));
}

__global__ void prep_x(const float* __restrict__ embed, const int* __restrict__ message)
{
    const int t = blockIdx.x;
    const int b = blockIdx.y;
    const int e = message[b * T_SZ + t];
    const float* src = embed + (size_t)e * EMB;
    const size_t o = ((size_t)t * B_SZ + b) * EMB;
    for (int k = threadIdx.x; k < EMB; k += blockDim.x) {
        const float v = src[k];
        const __nv_bfloat16 hi = __float2bfloat16(v);
        g_Xhi[o + k] = hi;
        g_Xlo[o + k] = __float2bfloat16(v - __bfloat162float(hi));
    }
}

__global__ void prep_misc(const float* __restrict__ b)
{
    int idx = blockIdx.x * blockDim.x + threadIdx.x;
    if (idx < GATES) {
        const int q = (idx >> 5) & 3, j = idx >> 7, l = idx & 31;
        const int n = q * 1024 + j * 32 + l;
        g_bp[idx] = b[n] + (q == 2 ? 1.0f : 0.0f);
    }
    if (idx < B_SZ * HID) {
        g_c[idx] = 0.0f;
        g_hbhi[0][idx] = __float2bfloat16(0.0f);
        g_hblo[0][idx] = __float2bfloat16(0.0f);
    }
}

// ================= SIMT fp32 GEMM for the two output projections =================
#define BM 128
#define BN 128
#define BK 16
template<int MODE>   // 0 = A param, 2 = A = g_hf
__global__ __launch_bounds__(256)
void gemm_k(const float* __restrict__ A,
            const float* __restrict__ W, const float* __restrict__ bias,
            float* __restrict__ Cout, int N, int K)
{
    __shared__ float As[BK][BM + 4];
    __shared__ float Bs[BK][BN];
    const int tid = threadIdx.x;
    const int bm = blockIdx.y * BM;
    const int bn = blockIdx.x * BN;

    const int ar0 = tid >> 2;
    const int ar1 = ar0 + 64;
    const int akq = (tid & 3) * 4;
    const float* Ab = (MODE == 2) ? (const float*)g_hf : A;
    const float* aE0 = Ab + (size_t)(bm + ar0) * K;
    const float* aE1 = Ab + (size_t)(bm + ar1) * K;

    const int br0 = tid >> 5;
    const int br1 = br0 + 8;
    const int bc  = (tid & 31) * 4;
    const int tm = (tid >> 4) * 8;
    const int tn = (tid & 15) * 8;

    float acc[8][8];
    #pragma unroll
    for (int i = 0; i < 8; i++)
        #pragma unroll
        for (int j = 0; j < 8; j++) acc[i][j] = 0.0f;

    for (int k0 = 0; k0 < K; k0 += BK) {
        const float4 va0 = *(const float4*)(aE0 + k0 + akq);
        const float4 va1 = *(const float4*)(aE1 + k0 + akq);
        const float4 vb0 = *(const float4*)(W + (size_t)(k0 + br0) * N + bn + bc);
        const float4 vb1 = *(const float4*)(W + (size_t)(k0 + br1) * N + bn + bc);
        As[akq + 0][ar0] = va0.x; As[akq + 1][ar0] = va0.y;
        As[akq + 2][ar0] = va0.z; As[akq + 3][ar0] = va0.w;
        As[akq + 0][ar1] = va1.x; As[akq + 1][ar1] = va1.y;
        As[akq + 2][ar1] = va1.z; As[akq + 3][ar1] = va1.w;
        *(float4*)&Bs[br0][bc] = vb0;
        *(float4*)&Bs[br1][bc] = vb1;
        __syncthreads();
        #pragma unroll
        for (int kk = 0; kk < BK; kk++) {
            float a[8], b[8];
            *(float4*)&a[0] = *(const float4*)&As[kk][tm];
            *(float4*)&a[4] = *(const float4*)&As[kk][tm + 4];
            *(float4*)&b[0] = *(const float4*)&Bs[kk][tn];
            *(float4*)&b[4] = *(const float4*)&Bs[kk][tn + 4];
            #pragma unroll
            for (int i = 0; i < 8; i++)
                #pragma unroll
                for (int j = 0; j < 8; j++)
                    acc[i][j] = fmaf(a[i], b[j], acc[i][j]);
        }
        __syncthreads();
    }
    float bia[8];
    *(float4*)&bia[0] = *(const float4*)(bias + bn + tn);
    *(float4*)&bia[4] = *(const float4*)(bias + bn + tn + 4);
    #pragma unroll
    for (int i = 0; i < 8; i++) {
        float4 o0, o1;
        o0.x = acc[i][0] + bia[0]; o0.y = acc[i][1] + bia[1];
        o0.z = acc[i][2] + bia[2]; o0.w = acc[i][3] + bia[3];
        o1.x = acc[i][4] + bia[4]; o1.y = acc[i][5] + bia[5];
        o1.z = acc[i][6] + bia[6]; o1.w = acc[i][7] + bia[7];
        float* crow = Cout + (size_t)(bm + tm + i) * N + bn + tn;
        *(float4*)(crow)     = o0;
        *(float4*)(crow + 4) = o1;
    }
}

// ================= launch =================
extern "C" void kernel_launch(void* const* d_in, const int* in_sizes, int n_in,
                              void* d_out, int out_size)
{
    const float* images  = (const float*)d_in[0];
    const float* embed   = (const float*)d_in[1];
    const float* W_cell  = (const float*)d_in[2];
    const float* b_cell  = (const float*)d_in[3];
    const float* W_img   = (const float*)d_in[4];
    const float* b_img   = (const float*)d_in[5];
    const float* W_hid   = (const float*)d_in[6];
    const float* b_hid   = (const float*)d_in[7];
    const int*   message = (const int*)d_in[8];
    float* out = (float*)d_out;
    (void)in_sizes; (void)n_in; (void)out_size;

    static int smem_set = 0;
    if (!smem_set) {
        cudaFuncSetAttribute(lstm_step, cudaFuncAttributeMaxDynamicSharedMemorySize, STEP_SMEM);
        smem_set = 1;
    }

    prep_misc<<<(B_SZ * HID + 255) / 256, 256>>>(b_cell);
    prep_w<<<(KCELL * GATES + 255) / 256, 256>>>(W_cell);
    prep_x<<<dim3(T_SZ, B_SZ), 128>>>(embed, message);

    gemm_k<0><<<dim3(1024 / BN, B_SZ / BM), 256>>>(images, W_img, b_img, out, 1024, 2048);

    for (int t = 0; t < T_SZ; t++)
        lstm_step<<<dim3(32, 4), 256, STEP_SMEM>>>(t);

    gemm_k<2><<<dim3(1024 / BN, B_SZ / BM), 256>>>(nullptr, W_hid, b_hid,
                                                   out + (size_t)B_SZ * HID, 1024, 1024);
}

// round 4
// speedup vs baseline: 2.0649x; 1.0254x over previous
#include <cuda_runtime.h>
#include <cuda_bf16.h>
#include <math.h>
#include <stdint.h>

#define B_SZ   512
#define T_SZ   128
#define HID    1024
#define EMB    512
#define GATES  4096
#define KCELL  1536
#define WK     1024      // recurrent K (h only)
#define NCH    16        // WK / 64

// ---------------- device scratch (allocation-free) ----------------
__device__ __nv_bfloat16 g_Whi[GATES * WK];      // [p][k'] permuted N-major (h part)
__device__ __nv_bfloat16 g_Wlo[GATES * WK];
__device__ float g_Ep[1024 * GATES];             // E'[vocab][p]: emb@Wx + b (+1 on f), permuted
__device__ __nv_bfloat16 g_hbhi[2][B_SZ * HID];  // double-buffered h (bf16 hi/lo)
__device__ __nv_bfloat16 g_hblo[2][B_SZ * HID];
__device__ float g_hf[B_SZ * HID];               // fp32 h (for final projection)
__device__ float g_c[B_SZ * HID];

// ---------------- helpers ----------------
__device__ __forceinline__ uint32_t smem_u32(const void* p) {
    uint32_t r;
    asm("{ .reg .u64 t; cvta.to.shared.u64 t, %1; cvt.u32.u64 %0, t; }" : "=r"(r) : "l"(p));
    return r;
}
__device__ __forceinline__ void cpa16(uint32_t dst, const void* src) {
    asm volatile("cp.async.cg.shared.global [%0], [%1], 16;" :: "r"(dst), "l"(src) : "memory");
}
#define CP_COMMIT() asm volatile("cp.async.commit_group;" ::: "memory")
#define CP_WAIT2()  asm volatile("cp.async.wait_group 2;" ::: "memory")
#define CP_WAIT1()  asm volatile("cp.async.wait_group 1;" ::: "memory")
#define CP_WAIT0()  asm volatile("cp.async.wait_group 0;" ::: "memory")

#define LDMX4(r, addr) \
    asm volatile("ldmatrix.sync.aligned.m8n8.x4.shared.b16 {%0,%1,%2,%3}, [%4];" \
        : "=r"((r)[0]), "=r"((r)[1]), "=r"((r)[2]), "=r"((r)[3]) : "r"(addr))

#define MMA(acc, a, b0, b1) \
    asm volatile("mma.sync.aligned.m16n8k16.row.col.f32.bf16.bf16.f32 " \
        "{%0,%1,%2,%3}, {%4,%5,%6,%7}, {%8,%9}, {%0,%1,%2,%3};" \
        : "+f"((acc)[0]), "+f"((acc)[1]), "+f"((acc)[2]), "+f"((acc)[3]) \
        : "r"((a)[0]), "r"((a)[1]), "r"((a)[2]), "r"((a)[3]), "r"(b0), "r"(b1))

#define SW(o) ((uint32_t)(o) ^ ((((uint32_t)(o)) >> 3) & 0x70))

__device__ __forceinline__ float sigm(float x) { return 1.0f / (1.0f + __expf(-x)); }
__device__ __forceinline__ float tanh_f(float x) {
    float e = __expf(2.0f * x);
    return 1.0f - 2.0f / (e + 1.0f);
}

// smem stage layout: 4 regions of 16KB (128 rows x 128B), 3 stages
#define OFF_AHI   0
#define OFF_ALO   16384
#define OFF_BHI   32768
#define OFF_BLO   49152
#define STAGE_SZ  65536
#define STEP_SMEM (3 * STAGE_SZ)   // 196608

// ================= fused LSTM step: h @ W_h (bf16 3-pass) + E' gather + pointwise =================
__global__ void __launch_bounds__(256, 1)
lstm_step(const int* __restrict__ message, int t)
{
    extern __shared__ __align__(1024) char smem[];
    const uint32_t sm = smem_u32(smem);
    const int tid  = threadIdx.x;
    const int lane = tid & 31;
    const int wid  = tid >> 5;
    const int bx   = blockIdx.x;           // n-tile 0..31 (permuted cols)
    const int bm   = blockIdx.y * 128;     // m-tile base row

    // ---- per-thread global source pointers (h rows + W rows) ----
    const int r    = tid >> 1;             // 0..127 tile row
    const int half = tid & 1;              // which 64B half of the 128B chunk row
    const char* aHhi = (const char*)(g_hbhi[t & 1] + (size_t)(bm + r) * HID);
    const char* aHlo = (const char*)(g_hblo[t & 1] + (size_t)(bm + r) * HID);
    const char* bWhi = (const char*)(g_Whi + (size_t)(bx * 128 + r) * WK);
    const char* bWlo = (const char*)(g_Wlo + (size_t)(bx * 128 + r) * WK);
    const uint32_t swoff[4] = {
        SW(r * 128 + half * 64 + 0),  SW(r * 128 + half * 64 + 16),
        SW(r * 128 + half * 64 + 32), SW(r * 128 + half * 64 + 48) };
    const int gb0 = half * 64;

    // ---- warp compute layout: 2(M) x 4(N) warps; warp tile 64x32 ----
    const int wm = (wid >> 2) * 64;
    const int wn = (wid & 3) * 32;

    float acc[4][4][4];
    #pragma unroll
    for (int i = 0; i < 4; i++)
        #pragma unroll
        for (int j = 0; j < 4; j++)
            #pragma unroll
            for (int k = 0; k < 4; k++) acc[i][j][k] = 0.0f;

    const int aRow = (lane & 15);
    const int aSel = ((lane >> 4) & 1) * 16;
    const int bRowBase = (lane & 7) + ((lane >> 4) & 1) * 8;
    const int bSel = ((lane >> 3) & 1) * 16;

    // ---- prefetch chunks 0,1 into slots 0,1 ----
    #pragma unroll
    for (int c = 0; c < 2; c++) {
        const uint32_t dst = sm + c * STAGE_SZ;
        const int kb = c * 128;
        #pragma unroll
        for (int u = 0; u < 4; u++) {
            const int gb = kb + gb0 + u * 16;
            cpa16(dst + OFF_AHI + swoff[u], aHhi + gb);
            cpa16(dst + OFF_ALO + swoff[u], aHlo + gb);
            cpa16(dst + OFF_BHI + swoff[u], bWhi + gb);
            cpa16(dst + OFF_BLO + swoff[u], bWlo + gb);
        }
        CP_COMMIT();
    }

    int sp = 2, sc = 0;
    #pragma unroll 1
    for (int c = 0; c < NCH; c++) {
        if (c < NCH - 2) {
            const uint32_t dst = sm + sp * STAGE_SZ;
            const int kb = (c + 2) * 128;
            #pragma unroll
            for (int u = 0; u < 4; u++) {
                const int gb = kb + gb0 + u * 16;
                cpa16(dst + OFF_AHI + swoff[u], aHhi + gb);
                cpa16(dst + OFF_ALO + swoff[u], aHlo + gb);
                cpa16(dst + OFF_BHI + swoff[u], bWhi + gb);
                cpa16(dst + OFF_BLO + swoff[u], bWlo + gb);
            }
            CP_COMMIT();
            CP_WAIT2();
        } else if (c == NCH - 2) {
            CP_WAIT1();
        } else {
            CP_WAIT0();
        }
        __syncthreads();   // chunk c visible to all warps

        const uint32_t stage = sm + sc * STAGE_SZ;
        #pragma unroll
        for (int k16 = 0; k16 < 4; k16++) {
            const int kb = k16 * 32;
            uint32_t ah[4][4], al[4][4], bh[2][4], bl[2][4];
            #pragma unroll
            for (int mi = 0; mi < 4; mi++) {
                const uint32_t ao = SW((wm + mi * 16 + aRow) * 128 + kb + aSel);
                LDMX4(ah[mi], stage + OFF_AHI + ao);
                LDMX4(al[mi], stage + OFF_ALO + ao);
            }
            #pragma unroll
            for (int nj = 0; nj < 2; nj++) {
                const uint32_t bo = SW((wn + nj * 16 + bRowBase) * 128 + kb + bSel);
                LDMX4(bh[nj], stage + OFF_BHI + bo);
                LDMX4(bl[nj], stage + OFF_BLO + bo);
            }
            #pragma unroll
            for (int mi = 0; mi < 4; mi++) {
                #pragma unroll
                for (int n8 = 0; n8 < 4; n8++) {
                    const uint32_t bh0 = bh[n8 >> 1][(n8 & 1) * 2];
                    const uint32_t bh1 = bh[n8 >> 1][(n8 & 1) * 2 + 1];
                    const uint32_t bl0 = bl[n8 >> 1][(n8 & 1) * 2];
                    const uint32_t bl1 = bl[n8 >> 1][(n8 & 1) * 2 + 1];
                    MMA(acc[mi][n8], ah[mi], bh0, bh1);
                    MMA(acc[mi][n8], al[mi], bh0, bh1);
                    MMA(acc[mi][n8], ah[mi], bl0, bl1);
                }
            }
        }
        __syncthreads();   // all warps done with slot sc before it is overwritten
        sp = (sp == 2) ? 0 : sp + 1;
        sc = (sc == 2) ? 0 : sc + 1;
    }

    // ---- stage accumulators to smem (fp32, stride 132) ----
    float* smC = (float*)smem;
    #pragma unroll
    for (int mi = 0; mi < 4; mi++) {
        #pragma unroll
        for (int n8 = 0; n8 < 4; n8++) {
            const int row = wm + mi * 16 + (lane >> 2);
            const int col = wn + n8 * 8 + (lane & 3) * 2;
            smC[row * 132 + col]           = acc[mi][n8][0];
            smC[row * 132 + col + 1]       = acc[mi][n8][1];
            smC[(row + 8) * 132 + col]     = acc[mi][n8][2];
            smC[(row + 8) * 132 + col + 1] = acc[mi][n8][3];
        }
    }
    __syncthreads();

    // ---- fused epilogue: + E'[msg] (has bias, +1 on f) then LSTM pointwise ----
    if (tid < 128) {
        const int row = bm + tid;
        const int msg = message[row * T_SZ + t];
        const float* cr = smC + tid * 132;
        const float* ep = g_Ep + (size_t)msg * GATES + bx * 128;
        float* crow = g_c + (size_t)row * HID + bx * 32;
        float* hrow = g_hf + (size_t)row * HID + bx * 32;
        __nv_bfloat16* hh = g_hbhi[(t + 1) & 1] + (size_t)row * HID + bx * 32;
        __nv_bfloat16* hl = g_hblo[(t + 1) & 1] + (size_t)row * HID + bx * 32;
        #pragma unroll 8
        for (int l = 0; l < 32; l++) {
            const float iv = cr[l]      + ep[l];
            const float gv = cr[32 + l] + ep[32 + l];
            const float fv = cr[64 + l] + ep[64 + l];   // bias + 1 already folded
            const float ov = cr[96 + l] + ep[96 + l];
            const float cc = sigm(fv) * crow[l] + sigm(iv) * tanh_f(gv);
            const float hv = sigm(ov) * tanh_f(cc);
            crow[l] = cc;
            hrow[l] = hv;
            const __nv_bfloat16 hi = __float2bfloat16(hv);
            hh[l] = hi;
            hl[l] = __float2bfloat16(hv - __bfloat162float(hi));
        }
    }
}

// ================= prep kernels =================
// W (h part, rows 512..1535): split + transpose + gate-permute
__global__ void prep_w(const float* __restrict__ W)
{
    int idx = blockIdx.x * blockDim.x + threadIdx.x;
    if (idx >= GATES * WK) return;
    const int p  = idx / WK;       // permuted col
    const int k  = idx % WK;       // 0..1023 (h part)
    const int q = (p >> 5) & 3, j = p >> 7, l = p & 31;
    const int n = q * 1024 + j * 32 + l;
    const float w = W[(size_t)(EMB + k) * GATES + n];
    const __nv_bfloat16 hi = __float2bfloat16(w);
    g_Whi[idx] = hi;
    g_Wlo[idx] = __float2bfloat16(w - __bfloat162float(hi));
}

__global__ void prep_misc()
{
    int idx = blockIdx.x * blockDim.x + threadIdx.x;
    if (idx < B_SZ * HID) {
        g_c[idx] = 0.0f;
        g_hbhi[0][idx] = __float2bfloat16(0.0f);
        g_hblo[0][idx] = __float2bfloat16(0.0f);
    }
}

// E'[v][p] = embed[v,:] @ W_cell[0:512, n(p)] + b[n] (+1 for f gate), fp32, 128x128 tiles
__global__ __launch_bounds__(256)
void prep_e(const float* __restrict__ A, const float* __restrict__ W,
            const float* __restrict__ bias)
{
    __shared__ float As[16][132];
    __shared__ float Bs[16][128];
    const int tid = threadIdx.x;
    const int bm = blockIdx.y * 128;
    const int bn = blockIdx.x * 128;
    const int K = EMB, N = GATES;

    const int ar0 = tid >> 2, ar1 = ar0 + 64, akq = (tid & 3) * 4;
    const int br0 = tid >> 5, br1 = br0 + 8, bc = (tid & 31) * 4;
    const int tm = (tid >> 4) * 8, tn = (tid & 15) * 8;

    float acc[8][8];
    #pragma unroll
    for (int i = 0; i < 8; i++)
        #pragma unroll
        for (int j = 0; j < 8; j++) acc[i][j] = 0.0f;

    for (int k0 = 0; k0 < K; k0 += 16) {
        const float4 va0 = *(const float4*)(A + (size_t)(bm + ar0) * K + k0 + akq);
        const float4 va1 = *(const float4*)(A + (size_t)(bm + ar1) * K + k0 + akq);
        const float4 vb0 = *(const float4*)(W + (size_t)(k0 + br0) * N + bn + bc);
        const float4 vb1 = *(const float4*)(W + (size_t)(k0 + br1) * N + bn + bc);
        As[akq + 0][ar0] = va0.x; As[akq + 1][ar0] = va0.y;
        As[akq + 2][ar0] = va0.z; As[akq + 3][ar0] = va0.w;
        As[akq + 0][ar1] = va1.x; As[akq + 1][ar1] = va1.y;
        As[akq + 2][ar1] = va1.z; As[akq + 3][ar1] = va1.w;
        *(float4*)&Bs[br0][bc] = vb0;
        *(float4*)&Bs[br1][bc] = vb1;
        __syncthreads();
        #pragma unroll
        for (int kk = 0; kk < 16; kk++) {
            float a[8], b[8];
            *(float4*)&a[0] = *(const float4*)&As[kk][tm];
            *(float4*)&a[4] = *(const float4*)&As[kk][tm + 4];
            *(float4*)&b[0] = *(const float4*)&Bs[kk][tn];
            *(float4*)&b[4] = *(const float4*)&Bs[kk][tn + 4];
            #pragma unroll
            for (int i = 0; i < 8; i++)
                #pragma unroll
                for (int j = 0; j < 8; j++)
                    acc[i][j] = fmaf(a[i], b[j], acc[i][j]);
        }
        __syncthreads();
    }

    // permuted store with folded bias (+1 on forget gate)
    const int q = bn >> 10;                         // constant per CTA column tile
    const float fadd = (q == 2) ? 1.0f : 0.0f;
    float bia[8];
    *(float4*)&bia[0] = *(const float4*)(bias + bn + tn);
    *(float4*)&bia[4] = *(const float4*)(bias + bn + tn + 4);
    const int n0 = bn + tn;
    const int j0 = (n0 >> 5) & 31, l0 = n0 & 31;
    const int p0 = j0 * 128 + q * 32 + l0;          // 8-run stays inside one 32-block
    #pragma unroll
    for (int i = 0; i < 8; i++) {
        const int v = bm + tm + i;
        float4 o0, o1;
        o0.x = acc[i][0] + bia[0] + fadd; o0.y = acc[i][1] + bia[1] + fadd;
        o0.z = acc[i][2] + bia[2] + fadd; o0.w = acc[i][3] + bia[3] + fadd;
        o1.x = acc[i][4] + bia[4] + fadd; o1.y = acc[i][5] + bia[5] + fadd;
        o1.z = acc[i][6] + bia[6] + fadd; o1.w = acc[i][7] + bia[7] + fadd;
        float* dst = g_Ep + (size_t)v * GATES + p0;
        *(float4*)(dst)     = o0;
        *(float4*)(dst + 4) = o1;
    }
}

// ================= 64x64-tile SIMT fp32 GEMM (output projections) =================
template<int MODE>   // 0 = A param, 2 = A = g_hf
__global__ __launch_bounds__(256)
void gemm64(const float* __restrict__ A, const float* __restrict__ W,
            const float* __restrict__ bias, float* __restrict__ C,
            int N, int K)
{
    __shared__ float As[16][68];
    __shared__ float Bs[16][64];
    const int tid = threadIdx.x;
    const int bm = blockIdx.y * 64;
    const int bn = blockIdx.x * 64;
    const float* Ab = (MODE == 2) ? (const float*)g_hf : A;

    const int ar = tid >> 2, ak = (tid & 3) * 4;
    const int br = tid >> 4, bc = (tid & 15) * 4;
    const int tm = (tid >> 4) * 4, tn = (tid & 15) * 4;

    float acc[4][4];
    #pragma unroll
    for (int i = 0; i < 4; i++)
        #pragma unroll
        for (int j = 0; j < 4; j++) acc[i][j] = 0.0f;

    for (int k0 = 0; k0 < K; k0 += 16) {
        const float4 va = *(const float4*)(Ab + (size_t)(bm + ar) * K + k0 + ak);
        const float4 vb = *(const float4*)(W + (size_t)(k0 + br) * N + bn + bc);
        As[ak + 0][ar] = va.x; As[ak + 1][ar] = va.y;
        As[ak + 2][ar] = va.z; As[ak + 3][ar] = va.w;
        *(float4*)&Bs[br][bc] = vb;
        __syncthreads();
        #pragma unroll
        for (int kk = 0; kk < 16; kk++) {
            float a[4], b[4];
            *(float4*)&a[0] = *(const float4*)&As[kk][tm];
            *(float4*)&b[0] = *(const float4*)&Bs[kk][tn];
            #pragma unroll
            for (int i = 0; i < 4; i++)
                #pragma unroll
                for (int j = 0; j < 4; j++)
                    acc[i][j] = fmaf(a[i], b[j], acc[i][j]);
        }
        __syncthreads();
    }
    float4 bia = *(const float4*)(bias + bn + tn);
    #pragma unroll
    for (int i = 0; i < 4; i++) {
        float4 o;
        o.x = acc[i][0] + bia.x; o.y = acc[i][1] + bia.y;
        o.z = acc[i][2] + bia.z; o.w = acc[i][3] + bia.w;
        *(float4*)(C + (size_t)(bm + tm + i) * N + bn + tn) = o;
    }
}

// ================= launch =================
extern "C" void kernel_launch(void* const* d_in, const int* in_sizes, int n_in,
                              void* d_out, int out_size)
{
    const float* images  = (const float*)d_in[0];
    const float* embed   = (const float*)d_in[1];
    const float* W_cell  = (const float*)d_in[2];
    const float* b_cell  = (const float*)d_in[3];
    const float* W_img   = (const float*)d_in[4];
    const float* b_img   = (const float*)d_in[5];
    const float* W_hid   = (const float*)d_in[6];
    const float* b_hid   = (const float*)d_in[7];
    const int*   message = (const int*)d_in[8];
    float* out = (float*)d_out;
    (void)in_sizes; (void)n_in; (void)out_size;

    static int smem_set = 0;
    if (!smem_set) {
        cudaFuncSetAttribute(lstm_step, cudaFuncAttributeMaxDynamicSharedMemorySize, STEP_SMEM);
        smem_set = 1;
    }

    prep_misc<<<(B_SZ * HID + 255) / 256, 256>>>();
    prep_w<<<(GATES * WK + 255) / 256, 256>>>(W_cell);
    prep_e<<<dim3(GATES / 128, 1024 / 128), 256>>>(embed, W_cell, b_cell);

    // images_encoded (independent of the loop)
    gemm64<0><<<dim3(1024 / 64, B_SZ / 64), 256>>>(images, W_img, b_img, out, 1024, 2048);

    for (int t = 0; t < T_SZ; t++)
        lstm_step<<<dim3(32, 4), 256, STEP_SMEM>>>(message, t);

    gemm64<2><<<dim3(1024 / 64, B_SZ / 64), 256>>>(nullptr, W_hid, b_hid,
                                                   out + (size_t)B_SZ * HID, 1024, 1024);
}

// round 6
// speedup vs baseline: 2.0856x; 1.0100x over previous
#include <cuda_runtime.h>
#include <cuda_bf16.h>
#include <math.h>
#include <stdint.h>

#define B_SZ   512
#define T_SZ   128
#define HID    1024
#define EMB    512
#define GATES  4096
#define WK     1024      // recurrent K (h only)
#define NCH    16        // chunks of 64 K-elems (WK / 64)

// ---------------- device scratch (allocation-free) ----------------
__device__ __nv_bfloat16 g_Whi[GATES * WK];      // [p][k'] permuted N-major (h part)
__device__ __nv_bfloat16 g_Wlo[GATES * WK];
__device__ float g_Ep[1024 * GATES];             // E'[vocab][p]: emb@Wx + b (+1 on f), permuted
__device__ __nv_bfloat16 g_hbhi[2][B_SZ * HID];  // double-buffered h (bf16 hi/lo)
__device__ __nv_bfloat16 g_hblo[2][B_SZ * HID];
__device__ float g_hf[B_SZ * HID];               // fp32 h (for final projection)
__device__ float g_c[B_SZ * HID];
__device__ unsigned g_bar;                       // device-wide step barrier

// ---------------- helpers ----------------
__device__ __forceinline__ uint32_t smem_u32(const void* p) {
    uint32_t r;
    asm("{ .reg .u64 t; cvta.to.shared.u64 t, %1; cvt.u32.u64 %0, t; }" : "=r"(r) : "l"(p));
    return r;
}
__device__ __forceinline__ void cpa16(uint32_t dst, const void* src) {
    asm volatile("cp.async.cg.shared.global [%0], [%1], 16;" :: "r"(dst), "l"(src) : "memory");
}
#define CP_COMMIT() asm volatile("cp.async.commit_group;" ::: "memory")
#define CP_WAIT2()  asm volatile("cp.async.wait_group 2;" ::: "memory")
#define CP_WAIT1()  asm volatile("cp.async.wait_group 1;" ::: "memory")
#define CP_WAIT0()  asm volatile("cp.async.wait_group 0;" ::: "memory")

#define LDMX4(r, addr) \
    asm volatile("ldmatrix.sync.aligned.m8n8.x4.shared.b16 {%0,%1,%2,%3}, [%4];" \
        : "=r"((r)[0]), "=r"((r)[1]), "=r"((r)[2]), "=r"((r)[3]) : "r"(addr))

#define MMA(acc, a, b0, b1) \
    asm volatile("mma.sync.aligned.m16n8k16.row.col.f32.bf16.bf16.f32 " \
        "{%0,%1,%2,%3}, {%4,%5,%6,%7}, {%8,%9}, {%0,%1,%2,%3};" \
        : "+f"((acc)[0]), "+f"((acc)[1]), "+f"((acc)[2]), "+f"((acc)[3]) \
        : "r"((a)[0]), "r"((a)[1]), "r"((a)[2]), "r"((a)[3]), "r"(b0), "r"(b1))

#define SW(o) ((uint32_t)(o) ^ ((((uint32_t)(o)) >> 3) & 0x70))

__device__ __forceinline__ float sigm(float x) { return 1.0f / (1.0f + __expf(-x)); }
__device__ __forceinline__ float tanh_f(float x) {
    float e = __expf(2.0f * x);
    return 1.0f - 2.0f / (e + 1.0f);
}

// smem: 3 stages; each stage = 4 regions (Ahi/Alo/Bhi/Blo) of 128 rows x 128B
#define OFF_AHI   0
#define OFF_ALO   16384
#define OFF_BHI   32768
#define OFF_BLO   49152
#define STAGE_SZ  65536
#define STEP_SMEM (3 * STAGE_SZ)   // 196608

// ================= persistent LSTM: all 128 steps in one kernel =================
__global__ void __launch_bounds__(256, 1)
lstm_persist(const int* __restrict__ message)
{
    extern __shared__ __align__(1024) char smem[];
    const uint32_t sm = smem_u32(smem);
    const int tid  = threadIdx.x;
    const int lane = tid & 31;
    const int wid  = tid >> 5;
    const int bx   = blockIdx.x;           // n-tile 0..31 (permuted cols)
    const int bm   = blockIdx.y * 128;     // m-tile base row

    // ---- fixed per-thread addressing: chunk = 64 K-elems = 128B per row ----
    const int r    = tid >> 1;             // 0..127 tile row
    const int half = tid & 1;              // which 64B half of the 128B chunk row
    const char* bWhi = (const char*)(g_Whi + (size_t)(bx * 128 + r) * WK);
    const char* bWlo = (const char*)(g_Wlo + (size_t)(bx * 128 + r) * WK);
    const char* hHi[2] = { (const char*)(g_hbhi[0] + (size_t)(bm + r) * HID),
                           (const char*)(g_hbhi[1] + (size_t)(bm + r) * HID) };
    const char* hLo[2] = { (const char*)(g_hblo[0] + (size_t)(bm + r) * HID),
                           (const char*)(g_hblo[1] + (size_t)(bm + r) * HID) };
    const uint32_t swoff[4] = {
        SW(r * 128 + half * 64 + 0),  SW(r * 128 + half * 64 + 16),
        SW(r * 128 + half * 64 + 32), SW(r * 128 + half * 64 + 48) };
    const int gb0 = half * 64;

    // ---- warp compute layout: 2(M) x 4(N) warps; warp tile 64x32 ----
    const int wm = (wid >> 2) * 64;
    const int wn = (wid & 3) * 32;
    const int aRow = (lane & 15);
    const int aSel = ((lane >> 4) & 1) * 16;
    const int bRowBase = (lane & 7) + ((lane >> 4) & 1) * 8;
    const int bSel = ((lane >> 3) & 1) * 16;

    // epilogue addressing (threads 0..127)
    const int erow = bm + tid;
    const int* msgp = message + erow * T_SZ;
    float* crow = g_c + (size_t)erow * HID + bx * 32;
    float* hrow = g_hf + (size_t)erow * HID + bx * 32;
    float* smC = (float*)smem;

    #pragma unroll 1
    for (int t = 0; t < T_SZ; t++) {
        const char* aHhi = hHi[t & 1];
        const char* aHlo = hLo[t & 1];

        float acc[4][4][4];
        #pragma unroll
        for (int i = 0; i < 4; i++)
            #pragma unroll
            for (int j = 0; j < 4; j++)
                #pragma unroll
                for (int k = 0; k < 4; k++) acc[i][j][k] = 0.0f;

        // ---- prefetch chunks 0,1 into slots 0,1 (128B per row each) ----
        #pragma unroll
        for (int c = 0; c < 2; c++) {
            const uint32_t dst = sm + c * STAGE_SZ;
            const int kb = c * 128;
            #pragma unroll
            for (int u = 0; u < 4; u++) {
                const int gb = kb + gb0 + u * 16;
                cpa16(dst + OFF_AHI + swoff[u], aHhi + gb);
                cpa16(dst + OFF_ALO + swoff[u], aHlo + gb);
                cpa16(dst + OFF_BHI + swoff[u], bWhi + gb);
                cpa16(dst + OFF_BLO + swoff[u], bWlo + gb);
            }
            CP_COMMIT();
        }

        int sc = 0, sp = 2;
        #pragma unroll 1
        for (int c = 0; c < NCH; c++) {
            // ensure chunk c has landed (own groups), then make it CTA-visible;
            // this same sync also proves every warp finished compute(c-1),
            // so slot sp (== slot of chunk c-1) is free to overwrite below.
            if (c < NCH - 2)      { CP_WAIT2(); }
            else if (c == NCH - 2){ CP_WAIT1(); }
            else                  { CP_WAIT0(); }
            __syncthreads();

            if (c + 2 < NCH) {
                const uint32_t dst = sm + sp * STAGE_SZ;
                const int kb = (c + 2) * 128;
                #pragma unroll
                for (int u = 0; u < 4; u++) {
                    const int gb = kb + gb0 + u * 16;
                    cpa16(dst + OFF_AHI + swoff[u], aHhi + gb);
                    cpa16(dst + OFF_ALO + swoff[u], aHlo + gb);
                    cpa16(dst + OFF_BHI + swoff[u], bWhi + gb);
                    cpa16(dst + OFF_BLO + swoff[u], bWlo + gb);
                }
                CP_COMMIT();
            }

            const uint32_t stage = sm + sc * STAGE_SZ;
            #pragma unroll
            for (int k16 = 0; k16 < 4; k16++) {
                const int kb = k16 * 32;
                uint32_t ah[4][4], al[4][4], bh[2][4], bl[2][4];
                #pragma unroll
                for (int mi = 0; mi < 4; mi++) {
                    const uint32_t ao = SW((wm + mi * 16 + aRow) * 128 + kb + aSel);
                    LDMX4(ah[mi], stage + OFF_AHI + ao);
                    LDMX4(al[mi], stage + OFF_ALO + ao);
                }
                #pragma unroll
                for (int nj = 0; nj < 2; nj++) {
                    const uint32_t bo = SW((wn + nj * 16 + bRowBase) * 128 + kb + bSel);
                    LDMX4(bh[nj], stage + OFF_BHI + bo);
                    LDMX4(bl[nj], stage + OFF_BLO + bo);
                }
                #pragma unroll
                for (int mi = 0; mi < 4; mi++) {
                    #pragma unroll
                    for (int n8 = 0; n8 < 4; n8++) {
                        const uint32_t bh0 = bh[n8 >> 1][(n8 & 1) * 2];
                        const uint32_t bh1 = bh[n8 >> 1][(n8 & 1) * 2 + 1];
                        const uint32_t bl0 = bl[n8 >> 1][(n8 & 1) * 2];
                        const uint32_t bl1 = bl[n8 >> 1][(n8 & 1) * 2 + 1];
                        MMA(acc[mi][n8], ah[mi], bh0, bh1);
                        MMA(acc[mi][n8], al[mi], bh0, bh1);
                        MMA(acc[mi][n8], ah[mi], bl0, bl1);
                    }
                }
            }
            sc = (sc == 2) ? 0 : sc + 1;
            sp = (sp == 2) ? 0 : sp + 1;
        }

        // ---- stage accumulators to smem (fp32, stride 132); overlaps stage slots ----
        __syncthreads();   // all warps finished reading stage slots
        #pragma unroll
        for (int mi = 0; mi < 4; mi++) {
            #pragma unroll
            for (int n8 = 0; n8 < 4; n8++) {
                const int row = wm + mi * 16 + (lane >> 2);
                const int col = wn + n8 * 8 + (lane & 3) * 2;
                smC[row * 132 + col]           = acc[mi][n8][0];
                smC[row * 132 + col + 1]       = acc[mi][n8][1];
                smC[(row + 8) * 132 + col]     = acc[mi][n8][2];
                smC[(row + 8) * 132 + col + 1] = acc[mi][n8][3];
            }
        }
        __syncthreads();

        // ---- fused epilogue: + E'[msg] (bias, +1 on f folded) then LSTM pointwise ----
        if (tid < 128) {
            const int msg = msgp[t];
            const float* cr = smC + tid * 132;
            const float* ep = g_Ep + (size_t)msg * GATES + bx * 128;
            __nv_bfloat16* hh = g_hbhi[(t + 1) & 1] + (size_t)erow * HID + bx * 32;
            __nv_bfloat16* hl = g_hblo[(t + 1) & 1] + (size_t)erow * HID + bx * 32;
            #pragma unroll 8
            for (int l = 0; l < 32; l++) {
                const float iv = cr[l]      + ep[l];
                const float gv = cr[32 + l] + ep[32 + l];
                const float fv = cr[64 + l] + ep[64 + l];
                const float ov = cr[96 + l] + ep[96 + l];
                const float cc = sigm(fv) * crow[l] + sigm(iv) * tanh_f(gv);
                const float hv = sigm(ov) * tanh_f(cc);
                crow[l] = cc;
                hrow[l] = hv;
                const __nv_bfloat16 hi = __float2bfloat16(hv);
                hh[l] = hi;
                hl[l] = __float2bfloat16(hv - __bfloat162float(hi));
            }
        }

        // ---- device-wide step barrier (skip after last step) ----
        if (t + 1 < T_SZ) {
            __threadfence();
            __syncthreads();
            if (tid == 0) {
                atomicAdd(&g_bar, 1u);
                const unsigned target = 128u * (unsigned)(t + 1);
                while (*(volatile unsigned*)&g_bar < target) { __nanosleep(64); }
            }
            __syncthreads();
        }
    }
}

// ================= prep kernels =================
__global__ void prep_w(const float* __restrict__ W)
{
    int idx = blockIdx.x * blockDim.x + threadIdx.x;
    if (idx >= GATES * WK) return;
    const int p  = idx / WK;
    const int k  = idx % WK;
    const int q = (p >> 5) & 3, j = p >> 7, l = p & 31;
    const int n = q * 1024 + j * 32 + l;
    const float w = W[(size_t)(EMB + k) * GATES + n];
    const __nv_bfloat16 hi = __float2bfloat16(w);
    g_Whi[idx] = hi;
    g_Wlo[idx] = __float2bfloat16(w - __bfloat162float(hi));
}

__global__ void prep_misc()
{
    int idx = blockIdx.x * blockDim.x + threadIdx.x;
    if (idx == 0) g_bar = 0u;
    if (idx < B_SZ * HID) {
        g_c[idx] = 0.0f;
        g_hbhi[0][idx] = __float2bfloat16(0.0f);
        g_hblo[0][idx] = __float2bfloat16(0.0f);
    }
}

// E'[v][p] = embed[v,:] @ W_cell[0:512, n(p)] + b[n] (+1 for f gate)
__global__ __launch_bounds__(256)
void prep_e(const float* __restrict__ A, const float* __restrict__ W,
            const float* __restrict__ bias)
{
    __shared__ float As[16][132];
    __shared__ float Bs[16][128];
    const int tid = threadIdx.x;
    const int bm = blockIdx.y * 128;
    const int bn = blockIdx.x * 128;
    const int K = EMB, N = GATES;

    const int ar0 = tid >> 2, ar1 = ar0 + 64, akq = (tid & 3) * 4;
    const int br0 = tid >> 5, br1 = br0 + 8, bc = (tid & 31) * 4;
    const int tm = (tid >> 4) * 8, tn = (tid & 15) * 8;

    float acc[8][8];
    #pragma unroll
    for (int i = 0; i < 8; i++)
        #pragma unroll
        for (int j = 0; j < 8; j++) acc[i][j] = 0.0f;

    for (int k0 = 0; k0 < K; k0 += 16) {
        const float4 va0 = *(const float4*)(A + (size_t)(bm + ar0) * K + k0 + akq);
        const float4 va1 = *(const float4*)(A + (size_t)(bm + ar1) * K + k0 + akq);
        const float4 vb0 = *(const float4*)(W + (size_t)(k0 + br0) * N + bn + bc);
        const float4 vb1 = *(const float4*)(W + (size_t)(k0 + br1) * N + bn + bc);
        As[akq + 0][ar0] = va0.x; As[akq + 1][ar0] = va0.y;
        As[akq + 2][ar0] = va0.z; As[akq + 3][ar0] = va0.w;
        As[akq + 0][ar1] = va1.x; As[akq + 1][ar1] = va1.y;
        As[akq + 2][ar1] = va1.z; As[akq + 3][ar1] = va1.w;
        *(float4*)&Bs[br0][bc] = vb0;
        *(float4*)&Bs[br1][bc] = vb1;
        __syncthreads();
        #pragma unroll
        for (int kk = 0; kk < 16; kk++) {
            float a[8], b[8];
            *(float4*)&a[0] = *(const float4*)&As[kk][tm];
            *(float4*)&a[4] = *(const float4*)&As[kk][tm + 4];
            *(float4*)&b[0] = *(const float4*)&Bs[kk][tn];
            *(float4*)&b[4] = *(const float4*)&Bs[kk][tn + 4];
            #pragma unroll
            for (int i = 0; i < 8; i++)
                #pragma unroll
                for (int j = 0; j < 8; j++)
                    acc[i][j] = fmaf(a[i], b[j], acc[i][j]);
        }
        __syncthreads();
    }

    const int q = bn >> 10;
    const float fadd = (q == 2) ? 1.0f : 0.0f;
    float bia[8];
    *(float4*)&bia[0] = *(const float4*)(bias + bn + tn);
    *(float4*)&bia[4] = *(const float4*)(bias + bn + tn + 4);
    const int n0 = bn + tn;
    const int j0 = (n0 >> 5) & 31, l0 = n0 & 31;
    const int p0 = j0 * 128 + q * 32 + l0;
    #pragma unroll
    for (int i = 0; i < 8; i++) {
        const int v = bm + tm + i;
        float4 o0, o1;
        o0.x = acc[i][0] + bia[0] + fadd; o0.y = acc[i][1] + bia[1] + fadd;
        o0.z = acc[i][2] + bia[2] + fadd; o0.w = acc[i][3] + bia[3] + fadd;
        o1.x = acc[i][4] + bia[4] + fadd; o1.y = acc[i][5] + bia[5] + fadd;
        o1.z = acc[i][6] + bia[6] + fadd; o1.w = acc[i][7] + bia[7] + fadd;
        float* dst = g_Ep + (size_t)v * GATES + p0;
        *(float4*)(dst)     = o0;
        *(float4*)(dst + 4) = o1;
    }
}

// ================= 64x64-tile SIMT fp32 GEMM (output projections) =================
template<int MODE>   // 0 = A param, 2 = A = g_hf
__global__ __launch_bounds__(256)
void gemm64(const float* __restrict__ A, const float* __restrict__ W,
            const float* __restrict__ bias, float* __restrict__ C,
            int N, int K)
{
    __shared__ float As[16][68];
    __shared__ float Bs[16][64];
    const int tid = threadIdx.x;
    const int bm = blockIdx.y * 64;
    const int bn = blockIdx.x * 64;
    const float* Ab = (MODE == 2) ? (const float*)g_hf : A;

    const int ar = tid >> 2, ak = (tid & 3) * 4;
    const int br = tid >> 4, bc = (tid & 15) * 4;
    const int tm = (tid >> 4) * 4, tn = (tid & 15) * 4;

    float acc[4][4];
    #pragma unroll
    for (int i = 0; i < 4; i++)
        #pragma unroll
        for (int j = 0; j < 4; j++) acc[i][j] = 0.0f;

    for (int k0 = 0; k0 < K; k0 += 16) {
        const float4 va = *(const float4*)(Ab + (size_t)(bm + ar) * K + k0 + ak);
        const float4 vb = *(const float4*)(W + (size_t)(k0 + br) * N + bn + bc);
        As[ak + 0][ar] = va.x; As[ak + 1][ar] = va.y;
        As[ak + 2][ar] = va.z; As[ak + 3][ar] = va.w;
        *(float4*)&Bs[br][bc] = vb;
        __syncthreads();
        #pragma unroll
        for (int kk = 0; kk < 16; kk++) {
            float a[4], b[4];
            *(float4*)&a[0] = *(const float4*)&As[kk][tm];
            *(float4*)&b[0] = *(const float4*)&Bs[kk][tn];
            #pragma unroll
            for (int i = 0; i < 4; i++)
                #pragma unroll
                for (int j = 0; j < 4; j++)
                    acc[i][j] = fmaf(a[i], b[j], acc[i][j]);
        }
        __syncthreads();
    }
    float4 bia = *(const float4*)(bias + bn + tn);
    #pragma unroll
    for (int i = 0; i < 4; i++) {
        float4 o;
        o.x = acc[i][0] + bia.x; o.y = acc[i][1] + bia.y;
        o.z = acc[i][2] + bia.z; o.w = acc[i][3] + bia.w;
        *(float4*)(C + (size_t)(bm + tm + i) * N + bn + tn) = o;
    }
}

// ================= launch =================
extern "C" void kernel_launch(void* const* d_in, const int* in_sizes, int n_in,
                              void* d_out, int out_size)
{
    const float* images  = (const float*)d_in[0];
    const float* embed   = (const float*)d_in[1];
    const float* W_cell  = (const float*)d_in[2];
    const float* b_cell  = (const float*)d_in[3];
    const float* W_img   = (const float*)d_in[4];
    const float* b_img   = (const float*)d_in[5];
    const float* W_hid   = (const float*)d_in[6];
    const float* b_hid   = (const float*)d_in[7];
    const int*   message = (const int*)d_in[8];
    float* out = (float*)d_out;
    (void)in_sizes; (void)n_in; (void)out_size;

    static int smem_set = 0;
    if (!smem_set) {
        cudaFuncSetAttribute(lstm_persist, cudaFuncAttributeMaxDynamicSharedMemorySize, STEP_SMEM);
        smem_set = 1;
    }

    prep_misc<<<(B_SZ * HID + 255) / 256, 256>>>();
    prep_w<<<(GATES * WK + 255) / 256, 256>>>(W_cell);
    prep_e<<<dim3(GATES / 128, 1024 / 128), 256>>>(embed, W_cell, b_cell);

    gemm64<0><<<dim3(1024 / 64, B_SZ / 64), 256>>>(images, W_img, b_img, out, 1024, 2048);

    lstm_persist<<<dim3(32, 4), 256, STEP_SMEM>>>(message);

    gemm64<2><<<dim3(1024 / 64, B_SZ / 64), 256>>>(nullptr, W_hid, b_hid,
                                                   out + (size_t)B_SZ * HID, 1024, 1024);
}